// round 7
// baseline (speedup 1.0000x reference)
#include <cuda_runtime.h>
#include <cstdint>

// DVBundle: free-running TMA-ring persistent kernel.
//
// w [4096, 8192, 4] f32 = 8192 float4 per neuron row (128KB).
// x [8192,4] -> 8 float4 per thread, held in REGISTERS.
// Output: [v_new (N) | r_new (N) | w_new (N*8192*4)]
//
// Grid = 148 persistent CTAs, 1024 threads. Row = 4 tiles of 32KB streamed
// via cp.async.bulk into a 7-deep smem ring. A ring slot stays live from its
// pass-1 read until its pass-2 read (w is LDS'd twice, never register-stashed),
// then a per-slot "empty" mbarrier (32 warp-arrives) releases it and tid0
// issues the refill (tile s+7). Only ONE full barrier per iteration (reduce);
// warps otherwise free-run, overlapping pass-2 stores with the next pass 1.

#define NI        8192
#define THREADS   1024
#define GRID      148
#define TILE_F4   2048               // 32KB tile
#define TILE_B    32768
#define NBUF      7

#define OFF_RING  0                              // 7 * 32768 = 229376
#define OFF_RED   (NBUF * TILE_B)                // 229376, 33*16 = 528
#define OFF_FULL  (OFF_RED + 33 * 16)            // 229904, 7*8
#define OFF_EMPTY (OFF_FULL + NBUF * 8)          // 229960
#define SMEM_B    (OFF_EMPTY + NBUF * 8)         // 230016

__device__ __forceinline__ void mbar_wait_acq(uint32_t mbar, uint32_t parity)
{
    uint32_t done;
    asm volatile(
        "{\n\t.reg .pred p;\n\t"
        "mbarrier.try_wait.parity.acquire.cta.shared::cta.b64 p, [%1], %2;\n\t"
        "selp.b32 %0, 1, 0, p;\n\t}"
        : "=r"(done) : "r"(mbar), "r"(parity) : "memory");
    if (!done) {
        asm volatile(
            "{\n\t.reg .pred P1;\n\t"
            "WL_%=:\n\t"
            "mbarrier.try_wait.parity.acquire.cta.shared::cta.b64 P1, [%0], %1, 0x989680;\n\t"
            "@P1 bra.uni WD_%=;\n\t"
            "bra.uni WL_%=;\n\t"
            "WD_%=:\n\t}"
            :: "r"(mbar), "r"(parity) : "memory");
    }
}

__device__ __forceinline__ void mbar_wait_rlx(uint32_t mbar, uint32_t parity)
{
    uint32_t done;
    asm volatile(
        "{\n\t.reg .pred p;\n\t"
        "mbarrier.try_wait.parity.relaxed.cta.shared::cta.b64 p, [%1], %2, 0x989680;\n\t"
        "selp.b32 %0, 1, 0, p;\n\t}"
        : "=r"(done) : "r"(mbar), "r"(parity) : "memory");
    if (!done) {
        asm volatile(
            "{\n\t.reg .pred P1;\n\t"
            "WL_%=:\n\t"
            "mbarrier.try_wait.parity.relaxed.cta.shared::cta.b64 P1, [%0], %1, 0x989680;\n\t"
            "@P1 bra.uni WD_%=;\n\t"
            "bra.uni WL_%=;\n\t"
            "WD_%=:\n\t}"
            :: "r"(mbar), "r"(parity) : "memory");
    }
}

// Issue TMA load of tile-stream index s into ring slot (s % 7).
__device__ __forceinline__ void issue_tile(int s, int ntiles, int bid,
                                           const float4* __restrict__ w,
                                           uint32_t smem_base, uint32_t mbar_full)
{
    if (s < ntiles) {
        const int      b  = s % NBUF;
        const uint32_t mb = mbar_full + 8u * b;
        asm volatile("mbarrier.arrive.expect_tx.shared.b64 _, [%0], %1;"
                     :: "r"(mb), "r"((uint32_t)TILE_B) : "memory");
        const void* src = (const void*)(w + (size_t)(bid + (s >> 2) * GRID) * NI
                                          + (size_t)(s & 3) * TILE_F4);
        asm volatile(
            "cp.async.bulk.shared::cluster.global.mbarrier::complete_tx::bytes "
            "[%0], [%1], %2, [%3];"
            :: "r"(smem_base + (uint32_t)(b * TILE_B)),
               "l"(src), "r"((uint32_t)TILE_B), "r"(mb) : "memory");
    }
}

__global__ __launch_bounds__(THREADS, 1)
void dvbundle_fr(const float4* __restrict__ w,
                 const float4* __restrict__ x,
                 const float*  __restrict__ v,
                 const float*  __restrict__ r,
                 float*        __restrict__ v_out,
                 float*        __restrict__ r_out,
                 float4*       __restrict__ w_out,
                 int n_neurons)
{
    extern __shared__ char smem[];
    float4* ring = (float4*)(smem + OFF_RING);
    float4* red  = (float4*)(smem + OFF_RED);

    const int tid  = threadIdx.x;
    const int warp = tid >> 5;
    const int lane = tid & 31;
    const int bid  = blockIdx.x;

    const uint32_t smem_base  = (uint32_t)__cvta_generic_to_shared(smem);
    const uint32_t mbar_full  = smem_base + OFF_FULL;
    const uint32_t mbar_empty = smem_base + OFF_EMPTY;

    // ---- x slice: permanent registers (8 float4 = 32 regs) ----
    float4 xr[8];
#pragma unroll
    for (int j = 0; j < 8; ++j)
        xr[j] = x[tid + j * THREADS];

    if (tid == 0) {
#pragma unroll
        for (int b = 0; b < NBUF; ++b) {
            asm volatile("mbarrier.init.shared.b64 [%0], %1;"
                         :: "r"(mbar_full + 8u * b), "r"(1u) : "memory");
            asm volatile("mbarrier.init.shared.b64 [%0], %1;"
                         :: "r"(mbar_empty + 8u * b), "r"(32u) : "memory");
        }
    }
    __syncthreads();

    const int niters = (n_neurons - bid + GRID - 1) / GRID;
    const int ntiles = 4 * niters;

    if (tid == 0) {
#pragma unroll
        for (int s = 0; s < NBUF; ++s)
            issue_tile(s, ntiles, bid, w, smem_base, mbar_full);
    }

    int n = bid;
    for (int it = 0; it < niters; ++it, n += GRID) {
        const float vn = v[n];
        const float rn = r[n];
        const int   s0 = 4 * it;

        // ---- Pass 1: 4 tiles, LDS -> FMA (no stash, slot stays live) ----
        float ax = 0.f, ay = 0.f, az = 0.f, aw = 0.f;
#pragma unroll
        for (int q = 0; q < 4; ++q) {
            const int s = s0 + q;
            const int b = s % NBUF;
            mbar_wait_acq(mbar_full + 8u * b, (uint32_t)(s / NBUF) & 1u);

            const float4* wb = ring + b * TILE_F4;
            const float4 w0 = wb[tid];
            const float4 w1 = wb[tid + THREADS];
            const float4 x0 = xr[2 * q];
            const float4 x1 = xr[2 * q + 1];
            ax = fmaf(w0.x, x0.x, ax); ax = fmaf(w1.x, x1.x, ax);
            ay = fmaf(w0.y, x0.y, ay); ay = fmaf(w1.y, x1.y, ay);
            az = fmaf(w0.z, x0.z, az); az = fmaf(w1.z, x1.z, az);
            aw = fmaf(w0.w, x0.w, aw); aw = fmaf(w1.w, x1.w, aw);
        }

        // ---- Reduce: warp shfl -> partials -> 1 barrier -> redundant reduce ----
#pragma unroll
        for (int o = 16; o > 0; o >>= 1) {
            ax += __shfl_xor_sync(0xffffffffu, ax, o);
            ay += __shfl_xor_sync(0xffffffffu, ay, o);
            az += __shfl_xor_sync(0xffffffffu, az, o);
            aw += __shfl_xor_sync(0xffffffffu, aw, o);
        }
        if (lane == 0) red[warp] = make_float4(ax, ay, az, aw);
        __syncthreads();

        float4 t = red[lane];
        float Ix = t.x, Iy = t.y, Iz = t.z, Iw = t.w;
#pragma unroll
        for (int o = 16; o > 0; o >>= 1) {
            Ix += __shfl_xor_sync(0xffffffffu, Ix, o);
            Iy += __shfl_xor_sync(0xffffffffu, Iy, o);
            Iz += __shfl_xor_sync(0xffffffffu, Iz, o);
            Iw += __shfl_xor_sync(0xffffffffu, Iw, o);
        }

        // ---- Scalar neuron update ----
        const float S    = Ix - Iy + Iz - Iw;
        const float dv   = (S - vn) * 0.05f;            // DT/TAU_V
        const float th   = tanhf(vn);
        const float actd = (vn > 0.f) ? (1.f - th * th) : 0.f;
        const float reg  = rn * actd * dv * 0.02f;      // / TAU_W

        if (tid == 0) {
            v_out[n] = vn + dv;
            r_out[n] = (vn > 0.f) ? th : 0.f;
        }

        // ---- Pass 2: re-LDS w from ring, update, STG; free slot; refill ----
        float4* wdst = w_out + (size_t)n * NI;
#pragma unroll
        for (int q = 0; q < 4; ++q) {
            const int s = s0 + q;
            const int b = s % NBUF;
            const float4* wb = ring + b * TILE_F4;
#pragma unroll
            for (int h = 0; h < 2; ++h) {
                const float4 wj = wb[tid + h * THREADS];
                const float4 xv = xr[2 * q + h];
                float4 o;
                o.x = fmaf(reg, fmaf(-wj.x, Ix, 0.5f * xv.x), wj.x);
                o.y = fmaf(reg, fmaf(-wj.y, Iy, 0.5f * xv.y), wj.y);
                o.z = fmaf(reg, fmaf(-wj.z, Iz, 0.5f * xv.z), wj.z);
                o.w = fmaf(reg, fmaf(-wj.w, Iw, 0.5f * xv.w), wj.w);
                wdst[q * TILE_F4 + h * THREADS + tid] = o;
            }
            __syncwarp();
            if (lane == 0)
                asm volatile("mbarrier.arrive.shared.b64 _, [%0];"
                             :: "r"(mbar_empty + 8u * b) : "memory");
            if (tid == 0) {
                mbar_wait_rlx(mbar_empty + 8u * b, (uint32_t)(s / NBUF) & 1u);
                issue_tile(s + NBUF, ntiles, bid, w, smem_base, mbar_full);
            }
        }
    }
}

extern "C" void kernel_launch(void* const* d_in, const int* in_sizes, int n_in,
                              void* d_out, int out_size)
{
    const float4* w = (const float4*)d_in[0];
    const float4* x = (const float4*)d_in[1];
    const float*  v = (const float*)d_in[2];
    const float*  r = (const float*)d_in[3];

    const int N = in_sizes[2];                 // 4096 neurons

    float*  out   = (float*)d_out;
    float*  v_out = out;
    float*  r_out = out + N;
    float4* w_out = (float4*)(out + 2 * (size_t)N);

    cudaFuncSetAttribute(dvbundle_fr,
                         cudaFuncAttributeMaxDynamicSharedMemorySize,
                         SMEM_B);

    dvbundle_fr<<<GRID, THREADS, SMEM_B>>>(w, x, v, r, v_out, r_out, w_out, N);
}

// round 8
// speedup vs baseline: 1.1103x; 1.1103x over previous
#include <cuda_runtime.h>
#include <cstdint>

// DVBundle: two-barrier TMA-ring persistent kernel.
//
// w [4096, 8192, 4] f32 = 8192 float4 per row (128KB = 4 tiles x 32KB).
// x [8192,4]: 8 float4 per thread, permanently in REGISTERS.
// Output: [v_new (N) | r_new (N) | w_new (N*8192*4)]
//
// Grid = 148 persistent CTAs, 1024 threads. 6-deep smem ring (192KB).
// Pass 1: per-tile mbarrier full-wait + LDS + FMA, NO barriers.
// Reduce: 1 __syncthreads. Pass 2: re-LDS w from live slot, update, STG.
// End-of-iteration __syncthreads proves all 4 slots consumed; tid0 then
// unconditionally issues the next 4 tile loads (slots freed by that proof).

#define NI        8192
#define THREADS   1024
#define GRID      148
#define TILE_F4   2048               // 32KB tile
#define TILE_B    32768
#define NBUF      6

#define OFF_RING  0                              // 6 * 32768 = 196608
#define OFF_RED   (NBUF * TILE_B)                // 196608, 33*16 = 528
#define OFF_MBAR  (OFF_RED + 33 * 16)            // 197136
#define SMEM_B    (OFF_MBAR + NBUF * 8)          // 197184

__device__ __forceinline__ void mbar_wait_acq(uint32_t mbar, uint32_t parity)
{
    uint32_t done;
    asm volatile(
        "{\n\t.reg .pred p;\n\t"
        "mbarrier.try_wait.parity.acquire.cta.shared::cta.b64 p, [%1], %2;\n\t"
        "selp.b32 %0, 1, 0, p;\n\t}"
        : "=r"(done) : "r"(mbar), "r"(parity) : "memory");
    if (!done) {
        asm volatile(
            "{\n\t.reg .pred P1;\n\t"
            "WL_%=:\n\t"
            "mbarrier.try_wait.parity.acquire.cta.shared::cta.b64 P1, [%0], %1, 0x989680;\n\t"
            "@P1 bra.uni WD_%=;\n\t"
            "bra.uni WL_%=;\n\t"
            "WD_%=:\n\t}"
            :: "r"(mbar), "r"(parity) : "memory");
    }
}

// Issue TMA load of tile-stream index s into ring slot (s % 6).
__device__ __forceinline__ void issue_tile(int s, int ntiles, int bid,
                                           const float4* __restrict__ w,
                                           uint32_t smem_base, uint32_t mbar_base)
{
    if (s < ntiles) {
        const int      b  = s % NBUF;
        const uint32_t mb = mbar_base + 8u * b;
        asm volatile("mbarrier.arrive.expect_tx.shared.b64 _, [%0], %1;"
                     :: "r"(mb), "r"((uint32_t)TILE_B) : "memory");
        const void* src = (const void*)(w + (size_t)(bid + (s >> 2) * GRID) * NI
                                          + (size_t)(s & 3) * TILE_F4);
        asm volatile(
            "cp.async.bulk.shared::cluster.global.mbarrier::complete_tx::bytes "
            "[%0], [%1], %2, [%3];"
            :: "r"(smem_base + (uint32_t)(b * TILE_B)),
               "l"(src), "r"((uint32_t)TILE_B), "r"(mb) : "memory");
    }
}

__global__ __launch_bounds__(THREADS, 1)
void dvbundle_2bar(const float4* __restrict__ w,
                   const float4* __restrict__ x,
                   const float*  __restrict__ v,
                   const float*  __restrict__ r,
                   float*        __restrict__ v_out,
                   float*        __restrict__ r_out,
                   float4*       __restrict__ w_out,
                   int n_neurons)
{
    extern __shared__ char smem[];
    float4* ring = (float4*)(smem + OFF_RING);
    float4* red  = (float4*)(smem + OFF_RED);

    const int tid  = threadIdx.x;
    const int warp = tid >> 5;
    const int lane = tid & 31;
    const int bid  = blockIdx.x;

    const uint32_t smem_base = (uint32_t)__cvta_generic_to_shared(smem);
    const uint32_t mbar_base = smem_base + OFF_MBAR;

    // ---- x slice: permanent registers (8 float4 = 32 regs) ----
    float4 xr[8];
#pragma unroll
    for (int j = 0; j < 8; ++j)
        xr[j] = x[tid + j * THREADS];

    if (tid == 0) {
#pragma unroll
        for (int b = 0; b < NBUF; ++b)
            asm volatile("mbarrier.init.shared.b64 [%0], %1;"
                         :: "r"(mbar_base + 8u * b), "r"(1u) : "memory");
    }
    __syncthreads();

    const int niters = (n_neurons - bid + GRID - 1) / GRID;
    const int ntiles = 4 * niters;

    if (tid == 0) {
#pragma unroll
        for (int s = 0; s < NBUF; ++s)
            issue_tile(s, ntiles, bid, w, smem_base, mbar_base);
    }

    int n = bid;
    for (int it = 0; it < niters; ++it, n += GRID) {
        const float vn = v[n];
        const float rn = r[n];
        const int   s0 = 4 * it;

        // ---- Pass 1: 4 tiles, mbar wait + LDS + FMA, no barriers ----
        float ax = 0.f, ay = 0.f, az = 0.f, aw = 0.f;
#pragma unroll
        for (int q = 0; q < 4; ++q) {
            const int s = s0 + q;
            const int b = s % NBUF;
            mbar_wait_acq(mbar_base + 8u * b, (uint32_t)(s / NBUF) & 1u);

            const float4* wb = ring + b * TILE_F4;
            const float4 w0 = wb[tid];
            const float4 w1 = wb[tid + THREADS];
            const float4 x0 = xr[2 * q];
            const float4 x1 = xr[2 * q + 1];
            ax = fmaf(w0.x, x0.x, ax); ax = fmaf(w1.x, x1.x, ax);
            ay = fmaf(w0.y, x0.y, ay); ay = fmaf(w1.y, x1.y, ay);
            az = fmaf(w0.z, x0.z, az); az = fmaf(w1.z, x1.z, az);
            aw = fmaf(w0.w, x0.w, aw); aw = fmaf(w1.w, x1.w, aw);
        }

        // ---- Reduce: shfl -> partials -> barrier #1 -> redundant reduce ----
#pragma unroll
        for (int o = 16; o > 0; o >>= 1) {
            ax += __shfl_xor_sync(0xffffffffu, ax, o);
            ay += __shfl_xor_sync(0xffffffffu, ay, o);
            az += __shfl_xor_sync(0xffffffffu, az, o);
            aw += __shfl_xor_sync(0xffffffffu, aw, o);
        }
        if (lane == 0) red[warp] = make_float4(ax, ay, az, aw);
        __syncthreads();

        float4 t = red[lane];
        float Ix = t.x, Iy = t.y, Iz = t.z, Iw = t.w;
#pragma unroll
        for (int o = 16; o > 0; o >>= 1) {
            Ix += __shfl_xor_sync(0xffffffffu, Ix, o);
            Iy += __shfl_xor_sync(0xffffffffu, Iy, o);
            Iz += __shfl_xor_sync(0xffffffffu, Iz, o);
            Iw += __shfl_xor_sync(0xffffffffu, Iw, o);
        }

        // ---- Scalar neuron update ----
        const float S    = Ix - Iy + Iz - Iw;
        const float dv   = (S - vn) * 0.05f;            // DT/TAU_V
        const float th   = tanhf(vn);
        const float actd = (vn > 0.f) ? (1.f - th * th) : 0.f;
        const float reg  = rn * actd * dv * 0.02f;      // / TAU_W

        if (tid == 0) {
            v_out[n] = vn + dv;
            r_out[n] = (vn > 0.f) ? th : 0.f;
        }

        // ---- Pass 2: re-LDS w from live slots, update, STG ----
        float4* wdst = w_out + (size_t)n * NI;
#pragma unroll
        for (int q = 0; q < 4; ++q) {
            const int b = (s0 + q) % NBUF;
            const float4* wb = ring + b * TILE_F4;
#pragma unroll
            for (int h = 0; h < 2; ++h) {
                const float4 wj = wb[tid + h * THREADS];
                const float4 xv = xr[2 * q + h];
                float4 o;
                o.x = fmaf(reg, fmaf(-wj.x, Ix, 0.5f * xv.x), wj.x);
                o.y = fmaf(reg, fmaf(-wj.y, Iy, 0.5f * xv.y), wj.y);
                o.z = fmaf(reg, fmaf(-wj.z, Iz, 0.5f * xv.z), wj.z);
                o.w = fmaf(reg, fmaf(-wj.w, Iw, 0.5f * xv.w), wj.w);
                wdst[q * TILE_F4 + h * THREADS + tid] = o;
            }
        }

        // ---- Barrier #2: all 4 slots of this row consumed -> refill ----
        __syncthreads();
        if (tid == 0) {
            issue_tile(s0 + 6, ntiles, bid, w, smem_base, mbar_base);
            issue_tile(s0 + 7, ntiles, bid, w, smem_base, mbar_base);
            issue_tile(s0 + 8, ntiles, bid, w, smem_base, mbar_base);
            issue_tile(s0 + 9, ntiles, bid, w, smem_base, mbar_base);
        }
    }
}

extern "C" void kernel_launch(void* const* d_in, const int* in_sizes, int n_in,
                              void* d_out, int out_size)
{
    const float4* w = (const float4*)d_in[0];
    const float4* x = (const float4*)d_in[1];
    const float*  v = (const float*)d_in[2];
    const float*  r = (const float*)d_in[3];

    const int N = in_sizes[2];                 // 4096 neurons

    float*  out   = (float*)d_out;
    float*  v_out = out;
    float*  r_out = out + N;
    float4* w_out = (float4*)(out + 2 * (size_t)N);

    cudaFuncSetAttribute(dvbundle_2bar,
                         cudaFuncAttributeMaxDynamicSharedMemorySize,
                         SMEM_B);

    dvbundle_2bar<<<GRID, THREADS, SMEM_B>>>(w, x, v, r, v_out, r_out, w_out, N);
}